// round 6
// baseline (speedup 1.0000x reference)
#include <cuda_runtime.h>
#include <cuda_bf16.h>

// Fixed shapes from setup_inputs
#define BB 8
#define KK 8
#define HH 1024
#define WW 1024
#define CH 4                  // rows per block chunk
#define NBY (HH / CH)         // 256 blocks along H
#define NBLOCKS (NBY * BB)    // 2048 total
#define GAMMA_C 10.0f
#define EPS_SQRT_C 1e-24f

// Per-block partials: [y][b*16 + q]; q<8: nom[k], q>=8: den[k]
__device__ float g_part[NBY * BB * 16];
__device__ unsigned int g_count = 0;   // zero-initialized; last block resets it

__global__ __launch_bounds__(256, 3) void clustering_fused_kernel(
    const float* __restrict__ img,      // (B,1,H,W)
    const float* __restrict__ spacing,  // (2,)
    const float* __restrict__ p,        // (B,K,H,W)
    float* __restrict__ out)
{
    const int b    = blockIdx.z;
    const int h0   = blockIdx.y * CH;
    const int w0   = 4 * threadIdx.x;        // 256 threads cover W=1024 via float4
    const int lane = threadIdx.x & 31;
    const bool lastcol = (w0 + 4 >= WW);

    const float sx = spacing[0];
    const float sy = spacing[1];
    const float smin   = fminf(sx, sy);
    const float inv_sx = 1.0f / sx;
    const float inv_sy = 1.0f / sy;

    const float* __restrict__ Ib = img + (size_t)b * HH * WW;
    const float* __restrict__ pb = p   + (size_t)b * KK * HH * WW;

    float nom[KK], den[KK];
#pragma unroll
    for (int k = 0; k < KK; k++) { nom[k] = 0.0f; den[k] = 0.0f; }

    for (int r = 0; r < CH; r++) {
        const int h  = h0 + r;
        const int hp = (h + 1 < HH) ? (h + 1) : (HH - 1);
        const size_t offC = (size_t)h  * WW + w0;
        const size_t offN = (size_t)hp * WW + w0;

        // ---- image rows: h (L1 hit after first iter) and h+1 ----
        const float4 iC = *(const float4*)(Ib + offC);
        const float4 iN = *(const float4*)(Ib + offN);

        float iR = __shfl_down_sync(0xFFFFFFFFu, iC.x, 1);
        if (lane == 31)
            iR = lastcol ? iC.w : __ldg(Ib + offC + 4);

        // ---- edge weights + (1+2w), shared across all K channels ----
        float wE[4], tE[4];
        {
            const float ix[4] = { iN.x - iC.x, iN.y - iC.y, iN.z - iC.z, iN.w - iC.w };
            const float iy[4] = { iC.y - iC.x, iC.z - iC.y, iC.w - iC.z, iR   - iC.w };
#pragma unroll
            for (int j = 0; j < 4; j++) {
                const float gx  = ix[j] * inv_sx;
                const float gy  = iy[j] * inv_sy;
                const float gn2 = gx * gx + gy * gy;
                const float gnI = sqrtf(fmaxf(gn2, EPS_SQRT_C));
                wE[j] = 1.0f / (1.0f + GAMMA_C * gnI * smin);
                tE[j] = 1.0f + 2.0f * wE[j];
            }
        }

#pragma unroll
        for (int k = 0; k < KK; k++) {
            const float* __restrict__ pk = pb + (size_t)k * HH * WW;
            const float4 pC = *(const float4*)(pk + offC);   // L1 hit after iter 0
            const float4 pN = *(const float4*)(pk + offN);   // DRAM stream

            float pR = __shfl_down_sync(0xFFFFFFFFu, pC.x, 1);
            if (lane == 31)
                pR = lastcol ? pC.w : __ldg(pk + offC + 4);

            const float pc[4] = { pC.x, pC.y, pC.z, pC.w };
            const float pn[4] = { pN.x, pN.y, pN.z, pN.w };
            const float pr[4] = { pC.y, pC.z, pC.w, pR  };   // right neighbors

            float n = 0.0f, d = 0.0f;
#pragma unroll
            for (int j = 0; j < 4; j++) {
                // pxp + pyp = (pn + pr) - 2*pc
                const float s2  = pn[j] + pr[j];
                const float dif = fmaf(-2.0f, pc[j], s2);
                n += pc[j] * fmaf(wE[j], dif, pc[j]);
                d += pc[j] * tE[j];
            }
            nom[k] += n;
            den[k] += d;
        }
    }

    // ---- Block reduction of the 16 quantities ----
    __shared__ float sred[8][16];
    const int warp = threadIdx.x >> 5;

#pragma unroll
    for (int q = 0; q < 16; q++) {
        float v = (q < 8) ? nom[q] : den[q - 8];
#pragma unroll
        for (int off = 16; off > 0; off >>= 1)
            v += __shfl_xor_sync(0xFFFFFFFFu, v, off);
        if (lane == 0) sred[warp][q] = v;
    }
    __syncthreads();

    if (threadIdx.x < 16) {
        const int q = threadIdx.x;
        float v = 0.0f;
#pragma unroll
        for (int wp = 0; wp < 8; wp++) v += sred[wp][q];
        g_part[(size_t)blockIdx.y * (BB * 16) + b * 16 + q] = v;
    }

    // ---- Last-block finalize (ticket pattern; counter self-resets) ----
    __shared__ bool s_last;
    __threadfence();
    __syncthreads();
    if (threadIdx.x == 0) {
        unsigned int ticket = atomicAdd(&g_count, 1u);
        s_last = (ticket == NBLOCKS - 1);
    }
    __syncthreads();

    if (s_last) {
        __shared__ float s[256];
        __shared__ float c[BB * KK];
        const int t = threadIdx.x;
        const int q    = t & 127;
        const int half = t >> 7;

        float v = 0.0f;
#pragma unroll 16
        for (int y = half * (NBY / 2); y < (half + 1) * (NBY / 2); y++)
            v += g_part[(size_t)y * (BB * 16) + q];
        s[t] = v;
        __syncthreads();

        if (t < BB * KK) {
            const int bb = t >> 3, kk = t & 7;
            const float tn = s[bb * 16 + kk]     + s[128 + bb * 16 + kk];
            const float td = s[bb * 16 + 8 + kk] + s[128 + bb * 16 + 8 + kk];
            c[t] = tn / td;                // cut_cost[b,k]
        }
        __syncthreads();

        if (t == 0) {
            float sum = 0.0f;
            for (int j = 0; j < BB * KK; j++) sum += c[j];
            out[0] = (float)(BB * KK) - sum;
            g_count = 0;                   // reset for next graph replay
        }
    }
}

extern "C" void kernel_launch(void* const* d_in, const int* in_sizes, int n_in,
                              void* d_out, int out_size) {
    const float* img     = (const float*)d_in[0];  // (8,1,1024,1024)
    const float* spacing = (const float*)d_in[1];  // (2,)
    const float* p       = (const float*)d_in[2];  // (8,8,1024,1024)
    float* out = (float*)d_out;

    dim3 grid(1, NBY, BB);   // (1, 256, 8) = 2048 blocks
    clustering_fused_kernel<<<grid, 256>>>(img, spacing, p, out);
}

// round 7
// speedup vs baseline: 1.1917x; 1.1917x over previous
#include <cuda_runtime.h>
#include <cuda_bf16.h>

// Fixed shapes from setup_inputs
#define BB 8
#define KK 8
#define HH 1024
#define WW 1024
#define CH 8                  // rows per block chunk (R3's proven config)
#define NBY (HH / CH)         // 128 blocks along H
#define NBLOCKS (NBY * BB)    // 1024 total
#define GAMMA_C 10.0f
#define EPS_SQRT_C 1e-24f

// Per-block partials: [y][b*16 + q]; q<8: nom[k], q>=8: den[k]
__device__ float g_part[NBY * BB * 16];
__device__ unsigned int g_count = 0;   // zero-initialized; last block resets it

__global__ __launch_bounds__(256, 2) void clustering_fused_kernel(
    const float* __restrict__ img,      // (B,1,H,W)
    const float* __restrict__ spacing,  // (2,)
    const float* __restrict__ p,        // (B,K,H,W)
    float* __restrict__ out)
{
    const int b    = blockIdx.z;
    const int h0   = blockIdx.y * CH;
    const int w0   = 4 * threadIdx.x;        // 256 threads cover W=1024 via float4
    const int lane = threadIdx.x & 31;
    const bool lastcol = (w0 + 4 >= WW);

    const float sx = spacing[0];
    const float sy = spacing[1];
    const float smin   = fminf(sx, sy);
    const float inv_sx = 1.0f / sx;
    const float inv_sy = 1.0f / sy;

    const float* __restrict__ Ib = img + (size_t)b * HH * WW;
    const float* __restrict__ pb = p   + (size_t)b * KK * HH * WW;

    float nom[KK], den[KK];
#pragma unroll
    for (int k = 0; k < KK; k++) { nom[k] = 0.0f; den[k] = 0.0f; }

    // Prime current row registers (row h0)
    float4 iC = *(const float4*)(Ib + (size_t)h0 * WW + w0);
    float4 pC[KK];
#pragma unroll
    for (int k = 0; k < KK; k++)
        pC[k] = *(const float4*)(pb + (size_t)k * HH * WW + (size_t)h0 * WW + w0);

    for (int r = 0; r < CH; r++) {
        const int h  = h0 + r;
        const int hp = (h + 1 < HH) ? (h + 1) : (HH - 1);

        // ---- issue all 9 next-row loads up front (batched -> high MLP) ----
        float4 iN = *(const float4*)(Ib + (size_t)hp * WW + w0);
        float4 pN[KK];
#pragma unroll
        for (int k = 0; k < KK; k++)
            pN[k] = *(const float4*)(pb + (size_t)k * HH * WW + (size_t)hp * WW + w0);

        // ---- right-neighbor of current I row: shuffle of REGISTER state ----
        float iR = __shfl_down_sync(0xFFFFFFFFu, iC.x, 1);
        if (lane == 31)
            iR = lastcol ? iC.w : __ldg(Ib + (size_t)h * WW + w0 + 4);

        // ---- edge weights + (1+2w), reused across all K channels ----
        float wE[4], tE[4];
        {
            const float ix[4] = { iN.x - iC.x, iN.y - iC.y, iN.z - iC.z, iN.w - iC.w };
            const float iy[4] = { iC.y - iC.x, iC.z - iC.y, iC.w - iC.z, iR   - iC.w };
#pragma unroll
            for (int j = 0; j < 4; j++) {
                const float gx  = ix[j] * inv_sx;
                const float gy  = iy[j] * inv_sy;
                const float gn2 = gx * gx + gy * gy;
                const float gnI = sqrtf(fmaxf(gn2, EPS_SQRT_C));
                wE[j] = 1.0f / (1.0f + GAMMA_C * gnI * smin);
                tE[j] = 1.0f + 2.0f * wE[j];
            }
        }

#pragma unroll
        for (int k = 0; k < KK; k++) {
            // shuffle of register-resident row (no fresh-load dependency)
            float pR = __shfl_down_sync(0xFFFFFFFFu, pC[k].x, 1);
            if (lane == 31)
                pR = lastcol ? pC[k].w
                             : __ldg(pb + (size_t)k * HH * WW + (size_t)h * WW + w0 + 4);

            const float pc[4] = { pC[k].x, pC[k].y, pC[k].z, pC[k].w };
            const float pn[4] = { pN[k].x, pN[k].y, pN[k].z, pN[k].w };
            const float pr[4] = { pC[k].y, pC[k].z, pC[k].w, pR };

            float n = 0.0f, d = 0.0f;
#pragma unroll
            for (int j = 0; j < 4; j++) {
                // pxp + pyp = (pn + pr) - 2*pc
                const float s2  = pn[j] + pr[j];
                const float dif = fmaf(-2.0f, pc[j], s2);
                n += pc[j] * fmaf(wE[j], dif, pc[j]);
                d += pc[j] * tE[j];
            }
            nom[k] += n;
            den[k] += d;

            pC[k] = pN[k];   // roll row registers
        }
        iC = iN;
    }

    // ---- Block reduction of the 16 quantities ----
    __shared__ float sred[8][16];
    const int warp = threadIdx.x >> 5;

#pragma unroll
    for (int q = 0; q < 16; q++) {
        float v = (q < 8) ? nom[q] : den[q - 8];
#pragma unroll
        for (int off = 16; off > 0; off >>= 1)
            v += __shfl_xor_sync(0xFFFFFFFFu, v, off);
        if (lane == 0) sred[warp][q] = v;
    }
    __syncthreads();

    if (threadIdx.x < 16) {
        const int q = threadIdx.x;
        float v = 0.0f;
#pragma unroll
        for (int wp = 0; wp < 8; wp++) v += sred[wp][q];
        g_part[(size_t)blockIdx.y * (BB * 16) + b * 16 + q] = v;
    }

    // ---- Last-block finalize (ticket pattern; counter self-resets) ----
    __shared__ bool s_last;
    __threadfence();
    __syncthreads();
    if (threadIdx.x == 0) {
        unsigned int ticket = atomicAdd(&g_count, 1u);
        s_last = (ticket == NBLOCKS - 1);
    }
    __syncthreads();

    if (s_last) {
        __shared__ float s[256];
        __shared__ float c[BB * KK];
        const int t = threadIdx.x;
        const int q    = t & 127;
        const int half = t >> 7;

        float v = 0.0f;
#pragma unroll 8
        for (int y = half * (NBY / 2); y < (half + 1) * (NBY / 2); y++)
            v += g_part[(size_t)y * (BB * 16) + q];
        s[t] = v;
        __syncthreads();

        if (t < BB * KK) {
            const int bb = t >> 3, kk = t & 7;
            const float tn = s[bb * 16 + kk]     + s[128 + bb * 16 + kk];
            const float td = s[bb * 16 + 8 + kk] + s[128 + bb * 16 + 8 + kk];
            c[t] = tn / td;                // cut_cost[b,k]
        }
        __syncthreads();

        if (t == 0) {
            float sum = 0.0f;
            for (int j = 0; j < BB * KK; j++) sum += c[j];
            out[0] = (float)(BB * KK) - sum;
            g_count = 0;                   // reset for next graph replay
        }
    }
}

extern "C" void kernel_launch(void* const* d_in, const int* in_sizes, int n_in,
                              void* d_out, int out_size) {
    const float* img     = (const float*)d_in[0];  // (8,1,1024,1024)
    const float* spacing = (const float*)d_in[1];  // (2,)
    const float* p       = (const float*)d_in[2];  // (8,8,1024,1024)
    float* out = (float*)d_out;

    dim3 grid(1, NBY, BB);   // (1, 128, 8) = 1024 blocks
    clustering_fused_kernel<<<grid, 256>>>(img, spacing, p, out);
}